// round 8
// baseline (speedup 1.0000x reference)
#include <cuda_runtime.h>
#include <cuda_bf16.h>
#include <cstdint>

// q,k,v: [2,12,2048,64] f32; mask: [2,1,1,2048] i32; bias: [1,12,2048,2048] f32
// out region: out [2,12,2048,64] then attn [2,12,2048,2048]
// attn = softmax((q/8)@k^T + bias, masked -> -10000); out = attn @ v
// No-max softmax; QK = 3-term bf16 hi/lo; PV = fp16 with 2^-5 pre-scale.
// All global loads prefetched >=1 tile ahead with PER-THREAD cp.async tracking
// (thread-exact smem slots -> no barrier on prefetch buffers). One barrier/tile
// via double-buffered bf16 K/V. tcgen05 unavailable -> mma.sync path.

#define TEMPERATURE 8.0f
#define NEG_FILL -10000.0f
#define ESCALE 0.03125f
#define ESCALE_INV 32.0f

constexpr int B_ = 2, H_ = 12, S_ = 2048, D_ = 64;
constexpr int TQ = 128, TK = 32;
constexpr int NKT = S_ / TK;             // 64 tiles
// byte offsets from 1024-aligned smem base; all bf16 tiles: 128B rows + XOR swizzle
constexpr int OFF_QHI  = 0;              // 128 x 128B = 16384
constexpr int OFF_QLO  = 16384;
constexpr int OFF_KHI0 = 32768;          // 32 x 128B = 4096 each
constexpr int OFF_KLO0 = 36864;
constexpr int OFF_VH0  = 40960;
constexpr int OFF_KHI1 = 45056;
constexpr int OFF_KLO1 = 49152;
constexpr int OFF_VH1  = 53248;
constexpr int OFF_RAWK = 57344;          // 32x64 f32 = 8192
constexpr int OFF_RAWV = 65536;          // 8192
constexpr int OFF_BIAS = 73728;          // 8 chunks x 256 thr x 8B = 16384 (thread-private)
constexpr int SMEM_DYN = 90112 + 1024;   // + alignment slack

// ---------- PTX helpers ----------
__device__ __forceinline__ uint32_t smem_u32(const void* p) {
    return (uint32_t)__cvta_generic_to_shared(p);
}
__device__ __forceinline__ uint32_t pack_bf16(float a, float b) {   // a -> low half
    uint32_t r;
    asm("cvt.rn.bf16x2.f32 %0, %1, %2;" : "=r"(r) : "f"(b), "f"(a));
    return r;
}
__device__ __forceinline__ uint32_t pack_f16(float a, float b) {    // a -> low half
    uint32_t r;
    asm("cvt.rn.f16x2.f32 %0, %1, %2;" : "=r"(r) : "f"(b), "f"(a));
    return r;
}
__device__ __forceinline__ void sts64(uint32_t a, uint32_t x, uint32_t y) {
    asm volatile("st.shared.v2.b32 [%0], {%1,%2};" :: "r"(a), "r"(x), "r"(y));
}
__device__ __forceinline__ float2 lds64f(uint32_t a) {
    float2 r;
    asm volatile("ld.shared.v2.f32 {%0,%1}, [%2];" : "=f"(r.x), "=f"(r.y) : "r"(a));
    return r;
}
__device__ __forceinline__ float4 lds128f(uint32_t a) {
    float4 r;
    asm volatile("ld.shared.v4.f32 {%0,%1,%2,%3}, [%4];"
                 : "=f"(r.x), "=f"(r.y), "=f"(r.z), "=f"(r.w) : "r"(a));
    return r;
}
__device__ __forceinline__ void ldsm_x4(uint32_t addr, uint32_t& r0, uint32_t& r1,
                                        uint32_t& r2, uint32_t& r3) {
    asm volatile("ldmatrix.sync.aligned.m8n8.x4.shared.b16 {%0,%1,%2,%3}, [%4];"
                 : "=r"(r0), "=r"(r1), "=r"(r2), "=r"(r3) : "r"(addr));
}
__device__ __forceinline__ void ldsm_x4t(uint32_t addr, uint32_t& r0, uint32_t& r1,
                                         uint32_t& r2, uint32_t& r3) {
    asm volatile("ldmatrix.sync.aligned.m8n8.x4.trans.shared.b16 {%0,%1,%2,%3}, [%4];"
                 : "=r"(r0), "=r"(r1), "=r"(r2), "=r"(r3) : "r"(addr));
}
__device__ __forceinline__ void mma_bf16(float& c0, float& c1, float& c2, float& c3,
                                         uint32_t a0, uint32_t a1, uint32_t a2, uint32_t a3,
                                         uint32_t b0, uint32_t b1) {
    asm volatile(
        "mma.sync.aligned.m16n8k16.row.col.f32.bf16.bf16.f32 "
        "{%0,%1,%2,%3}, {%4,%5,%6,%7}, {%8,%9}, {%0,%1,%2,%3};"
        : "+f"(c0), "+f"(c1), "+f"(c2), "+f"(c3)
        : "r"(a0), "r"(a1), "r"(a2), "r"(a3), "r"(b0), "r"(b1));
}
__device__ __forceinline__ void mma_f16(float& c0, float& c1, float& c2, float& c3,
                                        uint32_t a0, uint32_t a1, uint32_t a2, uint32_t a3,
                                        uint32_t b0, uint32_t b1) {
    asm volatile(
        "mma.sync.aligned.m16n8k16.row.col.f32.f16.f16.f32 "
        "{%0,%1,%2,%3}, {%4,%5,%6,%7}, {%8,%9}, {%0,%1,%2,%3};"
        : "+f"(c0), "+f"(c1), "+f"(c2), "+f"(c3)
        : "r"(a0), "r"(a1), "r"(a2), "r"(a3), "r"(b0), "r"(b1));
}
__device__ __forceinline__ void split2(float x, float& hi, float& lo) {
    hi = __bfloat162float(__float2bfloat16_rn(x));
    lo = x - hi;
}
__device__ __forceinline__ void cp_async16(uint32_t saddr, const void* gaddr) {
    asm volatile("cp.async.cg.shared.global [%0], [%1], 16;" :: "r"(saddr), "l"(gaddr));
}
__device__ __forceinline__ void cp_async8(uint32_t saddr, const void* gaddr) {
    asm volatile("cp.async.ca.shared.global [%0], [%1], 8;" :: "r"(saddr), "l"(gaddr));
}
__device__ __forceinline__ void cp_commit() {
    asm volatile("cp.async.commit_group;" ::: "memory");
}
__device__ __forceinline__ void cp_wait1() {
    asm volatile("cp.async.wait_group 1;" ::: "memory");
}

// ============== Fused kernel: e=exp(logits), rowsums, out, attn normalize =======
__global__ __launch_bounds__(256, 2) void attn_k1(
    const float* __restrict__ q, const float* __restrict__ k,
    const float* __restrict__ v, const int* __restrict__ mask,
    const float* __restrict__ bias, float* __restrict__ out,
    float* __restrict__ attn)
{
    extern __shared__ char dynraw[];
    __shared__ float row_inv[TQ];
    char* basep = (char*)(((uintptr_t)dynraw + 1023) & ~(uintptr_t)1023);
    const uint32_t sb = smem_u32(basep);

    const int t    = threadIdx.x;
    const int lane = t & 31;
    const int w    = t >> 5;            // 8 warps; warp owns q rows 16w..16w+15
    const int bh   = blockIdx.y;
    const int b    = bh & 1;            // b innermost -> bias shared in L2
    const int h    = bh >> 1;
    const int q0   = blockIdx.x * TQ;
    const int bhq  = b * H_ + h;

    const float* qb    = q    + ((long)bhq * S_ + q0) * D_;
    const float* kb    = k    + (long)bhq * S_ * D_;
    const float* vb    = v    + (long)bhq * S_ * D_;
    const int*   maskb = mask + (long)b * S_;
    float*       attb  = attn + ((long)bhq * S_ + q0) * S_;
    const float* biasb = bias + ((long)h  * S_ + q0) * S_;

    const int mrow = w * 16;
    const int g    = lane >> 2;
    const int qr0  = mrow + g;
    const int qr1  = qr0 + 8;

    // ---- prologue prefetch: rawKV(0) group, bias(0) group (both thread-exact) ----
    #pragma unroll
    for (int i = 0; i < 2; i++) {
        int idx4 = t + i * 256;          // 512 float4 = 32x64 f32 tile
        cp_async16(sb + OFF_RAWK + idx4 * 16u, kb + idx4 * 4);
        cp_async16(sb + OFF_RAWV + idx4 * 16u, vb + idx4 * 4);
    }
    cp_commit();                          // group: rawKV(0)
    #pragma unroll
    for (int j = 0; j < 8; j++) {
        int nt = j >> 1;
        int row = (j & 1) ? qr1 : qr0;
        cp_async8(sb + OFF_BIAS + j * 2048u + t * 8u,
                  biasb + (long)row * S_ + nt * 8 + (lane & 3) * 2);
    }
    cp_commit();                          // group: bias(0)

    // ---- load Q (scaled, hi/lo split), swizzled 128B rows ----
    #pragma unroll
    for (int i = 0; i < 8; i++) {
        int idx4 = t + i * 256;           // 2048 float4 = 128x64 f32
        int r  = idx4 >> 4;
        uint32_t cb = (uint32_t)(idx4 & 15) * 8u;
        uint32_t sw = (uint32_t)r * 128u + (cb ^ ((uint32_t)(r & 7) << 4));
        float4 qv = *(const float4*)(qb + idx4 * 4);
        float xh, xl, yh, yl, zh, zl, wh, wl;
        split2(qv.x * (1.0f / TEMPERATURE), xh, xl);
        split2(qv.y * (1.0f / TEMPERATURE), yh, yl);
        split2(qv.z * (1.0f / TEMPERATURE), zh, zl);
        split2(qv.w * (1.0f / TEMPERATURE), wh, wl);
        sts64(sb + OFF_QHI + sw, pack_bf16(xh, yh), pack_bf16(zh, wh));
        sts64(sb + OFF_QLO + sw, pack_bf16(xl, yl), pack_bf16(zl, wl));
    }

    // ---- fragment address precompute (single xorv works for Q, K, V) ----
    const uint32_t xorv = (uint32_t)(lane & 7) << 4;
    const uint32_t qhi_row = sb + OFF_QHI + (uint32_t)(mrow + (lane & 15)) * 128u;
    const uint32_t qlo_row = sb + OFF_QLO + (uint32_t)(mrow + (lane & 15)) * 128u;
    const uint32_t qcol0   = (uint32_t)(lane >> 4) * 16u;
    const int kgrp = lane >> 3;
    const uint32_t krow_off = (uint32_t)((kgrp >> 1) * 8 + (lane & 7)) * 128u;
    const uint32_t kcol0    = (uint32_t)(kgrp & 1) * 16u;
    const uint32_t vrow_off = (uint32_t)(lane & 15) * 128u;
    const uint32_t vcol0    = (uint32_t)(lane >> 4);

    float accO[8][4];
    #pragma unroll
    for (int i = 0; i < 8; i++)
        #pragma unroll
        for (int j = 0; j < 4; j++) accO[i][j] = 0.0f;
    float sum0 = 0.0f, sum1 = 0.0f;

    for (int kt = 0; kt < NKT; kt++) {
        const int k0 = kt * TK;
        const uint32_t bufb  = (kt & 1) ? (sb + OFF_KHI1) : (sb + OFF_KHI0);
        const uint32_t khi_a = bufb, klo_a = bufb + 4096u, vh_a = bufb + 8192u;

        // ---- 1. wait rawKV(kt) (own chunks only) + convert into buf[kt&1] ----
        cp_wait1();
        #pragma unroll
        for (int i = 0; i < 2; i++) {
            int idx4 = t + i * 256;
            int r  = idx4 >> 4;
            uint32_t cb = (uint32_t)(idx4 & 15) * 8u;
            uint32_t sw = (uint32_t)r * 128u + (cb ^ ((uint32_t)(r & 7) << 4));
            float4 kv = lds128f(sb + OFF_RAWK + idx4 * 16u);
            float xh, xl, yh, yl, zh, zl, wh, wl;
            split2(kv.x, xh, xl); split2(kv.y, yh, yl);
            split2(kv.z, zh, zl); split2(kv.w, wh, wl);
            sts64(khi_a + sw, pack_bf16(xh, yh), pack_bf16(zh, wh));
            sts64(klo_a + sw, pack_bf16(xl, yl), pack_bf16(zl, wl));
            float4 vv = lds128f(sb + OFF_RAWV + idx4 * 16u);
            sts64(vh_a + sw, pack_f16(vv.x, vv.y), pack_f16(vv.z, vv.w));
        }
        // ---- 2. prefetch rawKV(kt+1) (same thread-exact chunks) ----
        if (kt + 1 < NKT) {
            const float* kn = kb + (long)(k0 + TK) * D_;
            const float* vn = vb + (long)(k0 + TK) * D_;
            #pragma unroll
            for (int i = 0; i < 2; i++) {
                int idx4 = t + i * 256;
                cp_async16(sb + OFF_RAWK + idx4 * 16u, kn + idx4 * 4);
                cp_async16(sb + OFF_RAWV + idx4 * 16u, vn + idx4 * 4);
            }
        }
        cp_commit();   // group rawKV(kt+1) (possibly empty on last tile)

        // ---- 3. the one barrier: converts visible to all warps ----
        __syncthreads();

        // ---- 4. QK^T: 16(q) x 32(k) per warp, 3-term bf16 ----
        float acc[4][4];
        #pragma unroll
        for (int i = 0; i < 4; i++)
            #pragma unroll
            for (int j = 0; j < 4; j++) acc[i][j] = 0.0f;

        #pragma unroll
        for (int ks = 0; ks < 4; ks++) {
            uint32_t ah0, ah1, ah2, ah3, al0, al1, al2, al3;
            uint32_t qoff = (qcol0 + (uint32_t)ks * 32u) ^ xorv;
            ldsm_x4(qhi_row + qoff, ah0, ah1, ah2, ah3);
            ldsm_x4(qlo_row + qoff, al0, al1, al2, al3);
            #pragma unroll
            for (int ntp = 0; ntp < 4; ntp += 2) {
                uint32_t koff = krow_off + (uint32_t)ntp * 1024u
                              + ((kcol0 + (uint32_t)ks * 32u) ^ xorv);
                uint32_t bh0, bh1, bh2, bh3, bl0, bl1, bl2, bl3;
                ldsm_x4(khi_a + koff, bh0, bh1, bh2, bh3);
                ldsm_x4(klo_a + koff, bl0, bl1, bl2, bl3);
                mma_bf16(acc[ntp][0], acc[ntp][1], acc[ntp][2], acc[ntp][3],
                         ah0, ah1, ah2, ah3, bh0, bh1);
                mma_bf16(acc[ntp][0], acc[ntp][1], acc[ntp][2], acc[ntp][3],
                         ah0, ah1, ah2, ah3, bl0, bl1);
                mma_bf16(acc[ntp][0], acc[ntp][1], acc[ntp][2], acc[ntp][3],
                         al0, al1, al2, al3, bh0, bh1);
                mma_bf16(acc[ntp + 1][0], acc[ntp + 1][1], acc[ntp + 1][2], acc[ntp + 1][3],
                         ah0, ah1, ah2, ah3, bh2, bh3);
                mma_bf16(acc[ntp + 1][0], acc[ntp + 1][1], acc[ntp + 1][2], acc[ntp + 1][3],
                         ah0, ah1, ah2, ah3, bl2, bl3);
                mma_bf16(acc[ntp + 1][0], acc[ntp + 1][1], acc[ntp + 1][2], acc[ntp + 1][3],
                         al0, al1, al2, al3, bh2, bh3);
            }
        }

        // ---- 5. wait bias(kt) (own chunks), epilogue from smem slots ----
        cp_wait1();
        uint32_t efr[4][2];
        #pragma unroll
        for (int nt = 0; nt < 4; nt++) {
            const int gk = k0 + nt * 8 + (lane & 3) * 2;
            const int2 mv = *(const int2*)(maskb + gk);
            float2 bv0 = lds64f(sb + OFF_BIAS + (uint32_t)(nt * 2 + 0) * 2048u + t * 8u);
            float2 bv1 = lds64f(sb + OFF_BIAS + (uint32_t)(nt * 2 + 1) * 2048u + t * 8u);
            float l00 = acc[nt][0] + bv0.x; if (mv.x == 0) l00 = NEG_FILL;
            float l01 = acc[nt][1] + bv0.y; if (mv.y == 0) l01 = NEG_FILL;
            float l10 = acc[nt][2] + bv1.x; if (mv.x == 0) l10 = NEG_FILL;
            float l11 = acc[nt][3] + bv1.y; if (mv.y == 0) l11 = NEG_FILL;
            float e00 = __expf(l00), e01 = __expf(l01);
            float e10 = __expf(l10), e11 = __expf(l11);
            sum0 += e00 + e01;
            sum1 += e10 + e11;
            *(float2*)(attb + (long)qr0 * S_ + gk) = make_float2(e00, e01);
            *(float2*)(attb + (long)qr1 * S_ + gk) = make_float2(e10, e11);
            efr[nt][0] = pack_f16(e00 * ESCALE, e01 * ESCALE);
            efr[nt][1] = pack_f16(e10 * ESCALE, e11 * ESCALE);
        }
        // ---- 6. prefetch bias(kt+1) into own slots (no barrier: thread-private) ----
        if (kt + 1 < NKT) {
            #pragma unroll
            for (int j = 0; j < 8; j++) {
                int nt = j >> 1;
                int row = (j & 1) ? qr1 : qr0;
                cp_async8(sb + OFF_BIAS + j * 2048u + t * 8u,
                          biasb + (long)row * S_ + (k0 + TK) + nt * 8 + (lane & 3) * 2);
            }
        }
        cp_commit();   // group bias(kt+1) (possibly empty)

        // ---- 7. PV: out[16 x 64] += E[16 x 32] @ V[32 x 64], fp16 ----
        #pragma unroll
        for (int ks2 = 0; ks2 < 2; ks2++) {
            uint32_t a0 = efr[2 * ks2][0],     a1 = efr[2 * ks2][1];
            uint32_t a2 = efr[2 * ks2 + 1][0], a3 = efr[2 * ks2 + 1][1];
            #pragma unroll
            for (int dnp = 0; dnp < 8; dnp += 2) {
                uint32_t voff = vrow_off + (uint32_t)ks2 * 2048u
                              + (((vcol0 + (uint32_t)dnp) * 16u) ^ xorv);
                uint32_t b0, b1, b2, b3;
                ldsm_x4t(vh_a + voff, b0, b1, b2, b3);
                mma_f16(accO[dnp][0], accO[dnp][1], accO[dnp][2], accO[dnp][3],
                        a0, a1, a2, a3, b0, b1);
                mma_f16(accO[dnp + 1][0], accO[dnp + 1][1], accO[dnp + 1][2], accO[dnp + 1][3],
                        a0, a1, a2, a3, b2, b3);
            }
        }
    }

    // ---- row sums: reduce over quad ----
    sum0 += __shfl_xor_sync(0xffffffffu, sum0, 1);
    sum0 += __shfl_xor_sync(0xffffffffu, sum0, 2);
    sum1 += __shfl_xor_sync(0xffffffffu, sum1, 1);
    sum1 += __shfl_xor_sync(0xffffffffu, sum1, 2);
    const float inv0 = 1.0f / sum0;
    const float inv1 = 1.0f / sum1;
    if ((lane & 3) == 0) {
        row_inv[qr0] = inv0;
        row_inv[qr1] = inv1;
    }

    // ---- write out (normalized; ESCALE_INV undoes fp16 pre-scale) ----
    #pragma unroll
    for (int dn = 0; dn < 8; dn++) {
        const int dc = dn * 8 + (lane & 3) * 2;
        *(float2*)(out + ((long)bhq * S_ + q0 + qr0) * D_ + dc) =
            make_float2(accO[dn][0] * inv0 * ESCALE_INV, accO[dn][1] * inv0 * ESCALE_INV);
        *(float2*)(out + ((long)bhq * S_ + q0 + qr1) * D_ + dc) =
            make_float2(accO[dn][2] * inv1 * ESCALE_INV, accO[dn][3] * inv1 * ESCALE_INV);
    }

    // ---- fused normalize: scale own 128 attn rows in place ----
    __syncthreads();
    float4* ab4 = (float4*)attb;
    #pragma unroll 4
    for (int i4 = t; i4 < TQ * S_ / 4; i4 += 256) {
        const float inv = row_inv[i4 >> 9];
        float4 x = ab4[i4];
        x.x *= inv; x.y *= inv; x.z *= inv; x.w *= inv;
        ab4[i4] = x;
    }
}

extern "C" void kernel_launch(void* const* d_in, const int* in_sizes, int n_in,
                              void* d_out, int out_size) {
    const float* q    = (const float*)d_in[0];
    const float* k    = (const float*)d_in[1];
    const float* v    = (const float*)d_in[2];
    const int*   mask = (const int*)  d_in[3];
    const float* bias = (const float*)d_in[4];

    float* out  = (float*)d_out;
    float* attn = (float*)d_out + (long)B_ * H_ * S_ * D_;

    static int configured = 0;
    if (!configured) {
        cudaFuncSetAttribute(attn_k1,
                             cudaFuncAttributeMaxDynamicSharedMemorySize, SMEM_DYN);
        configured = 1;
    }

    dim3 grid(S_ / TQ, B_ * H_);        // (16, 24)
    attn_k1<<<grid, 256, SMEM_DYN>>>(q, k, v, mask, bias, out, attn);
}